// round 2
// baseline (speedup 1.0000x reference)
#include <cuda_runtime.h>
#include <cstdint>

#define NODES_MAX 50000
#define IN_C  128
#define HID_C 128
#define OUT_C 64

__device__ float g_h  [(size_t)NODES_MAX * HID_C];
__device__ float g_agg[(size_t)NODES_MAX * HID_C];
__device__ float g_h2 [(size_t)NODES_MAX * OUT_C];
__device__ int   g_idx_is64;

// If edge_index is int64 (values < 50000), every odd 32-bit word is 0.
// If int32, odd words are random node indices: 1024 consecutive zeros ~ never.
__global__ void detect_idx_kernel(const int* __restrict__ ei_words) {
    if (blockIdx.x == 0 && threadIdx.x == 0) {
        int is64 = 1;
        for (int i = 1; i < 2048; i += 2)
            if (ei_words[i] != 0) { is64 = 0; break; }
        g_idx_is64 = is64;
    }
}

// src index e: word e (i32) or word 2e (i64).
// dst index e: word E+e (i32) or word 2E+2e (i64).
__device__ __forceinline__ void load_sd(const int* __restrict__ ei, int e, int E,
                                        int is64, int& s, int& d) {
    if (is64) { s = ei[2 * e]; d = ei[2 * E + 2 * e]; }
    else      { s = ei[e];     d = ei[E + e]; }
}

__global__ void zero_agg_kernel(int n_float4) {
    float4* p = reinterpret_cast<float4*>(g_agg);
    int stride = gridDim.x * blockDim.x;
    for (int i = blockIdx.x * blockDim.x + threadIdx.x; i < n_float4; i += stride)
        p[i] = make_float4(0.f, 0.f, 0.f, 0.f);
}

__global__ void init_out_kernel(float* __restrict__ out,
                                const float* __restrict__ b2, int n_float4) {
    float4* o = reinterpret_cast<float4*>(out);
    const float4* b = reinterpret_cast<const float4*>(b2);
    int stride = gridDim.x * blockDim.x;
    for (int i = blockIdx.x * blockDim.x + threadIdx.x; i < n_float4; i += stride)
        o[i] = b[i & (OUT_C / 4 - 1)];
}

// GEMM1: h[M,128] = x[M,128] @ W1[128,128]. 64x128 tile, BK=32, 128 thr, 8x8 micro.
__global__ __launch_bounds__(128) void gemm1_kernel(
    const float* __restrict__ x, const float* __restrict__ W, int M)
{
    __shared__ float As[32][64];
    __shared__ float Bs[32][128];

    const int tid = threadIdx.x;
    const int ty  = tid >> 4;
    const int tx  = tid & 15;
    const int rowBase = blockIdx.x * 64;

    float acc[8][8];
#pragma unroll
    for (int i = 0; i < 8; i++)
#pragma unroll
        for (int j = 0; j < 8; j++) acc[i][j] = 0.f;

    for (int kt = 0; kt < IN_C; kt += 32) {
#pragma unroll
        for (int i = 0; i < 4; i++) {
            int idx = tid + i * 128;
            int r   = idx >> 3;
            int kv  = idx & 7;
            int grow = rowBase + r;
            float4 v = make_float4(0.f, 0.f, 0.f, 0.f);
            if (grow < M)
                v = *reinterpret_cast<const float4*>(x + (size_t)grow * IN_C + kt + kv * 4);
            As[kv * 4 + 0][r] = v.x;
            As[kv * 4 + 1][r] = v.y;
            As[kv * 4 + 2][r] = v.z;
            As[kv * 4 + 3][r] = v.w;
        }
#pragma unroll
        for (int i = 0; i < 8; i++) {
            int idx = tid + i * 128;
            int kk  = idx >> 5;
            int nv  = idx & 31;
            *reinterpret_cast<float4*>(&Bs[kk][nv * 4]) =
                *reinterpret_cast<const float4*>(W + (size_t)(kt + kk) * HID_C + nv * 4);
        }
        __syncthreads();

#pragma unroll
        for (int k = 0; k < 32; k++) {
            float a[8], b[8];
            *reinterpret_cast<float4*>(&a[0]) = *reinterpret_cast<float4*>(&As[k][ty * 8]);
            *reinterpret_cast<float4*>(&a[4]) = *reinterpret_cast<float4*>(&As[k][ty * 8 + 4]);
            *reinterpret_cast<float4*>(&b[0]) = *reinterpret_cast<float4*>(&Bs[k][tx * 8]);
            *reinterpret_cast<float4*>(&b[4]) = *reinterpret_cast<float4*>(&Bs[k][tx * 8 + 4]);
#pragma unroll
            for (int i = 0; i < 8; i++)
#pragma unroll
                for (int j = 0; j < 8; j++) acc[i][j] += a[i] * b[j];
        }
        __syncthreads();
    }

#pragma unroll
    for (int i = 0; i < 8; i++) {
        int grow = rowBase + ty * 8 + i;
        if (grow < M) {
#pragma unroll
            for (int j = 0; j < 8; j += 4)
                *reinterpret_cast<float4*>(g_h + (size_t)grow * HID_C + tx * 8 + j) =
                    make_float4(acc[i][j], acc[i][j + 1], acc[i][j + 2], acc[i][j + 3]);
        }
    }
}

// scatter1: agg[dst] += ew * h[src], 128 ch. One warp per edge, float4 per lane.
__global__ __launch_bounds__(256) void scatter1_kernel(
    const int* __restrict__ ei, const float* __restrict__ ew, int E)
{
    int e    = (blockIdx.x * blockDim.x + threadIdx.x) >> 5;
    int lane = threadIdx.x & 31;
    if (e >= E) return;
    int s, d;
    load_sd(ei, e, E, g_idx_is64, s, d);
    float w = ew[e];
    float4 v = *reinterpret_cast<const float4*>(g_h + (size_t)s * HID_C + lane * 4);
    v.x *= w; v.y *= w; v.z *= w; v.w *= w;
    float* a = g_agg + (size_t)d * HID_C + lane * 4;
    asm volatile("red.global.add.v4.f32 [%0], {%1,%2,%3,%4};"
                 :: "l"(a), "f"(v.x), "f"(v.y), "f"(v.z), "f"(v.w) : "memory");
}

// GEMM2: h2[M,64] = relu(agg[M,128]+b1) @ W2[128,64]. 128x64 tile, BK=32.
__global__ __launch_bounds__(128) void gemm2_kernel(
    const float* __restrict__ W2, const float* __restrict__ b1, int M)
{
    __shared__ float As[32][128];
    __shared__ float Bs[32][64];

    const int tid = threadIdx.x;
    const int ty  = tid >> 3;
    const int tx  = tid & 7;
    const int rowBase = blockIdx.x * 128;

    float acc[8][8];
#pragma unroll
    for (int i = 0; i < 8; i++)
#pragma unroll
        for (int j = 0; j < 8; j++) acc[i][j] = 0.f;

    for (int kt = 0; kt < HID_C; kt += 32) {
#pragma unroll
        for (int i = 0; i < 8; i++) {
            int idx = tid + i * 128;
            int r   = idx >> 3;
            int kv  = idx & 7;
            int grow = rowBase + r;
            float4 v = make_float4(0.f, 0.f, 0.f, 0.f);
            if (grow < M) {
                v = *reinterpret_cast<const float4*>(g_agg + (size_t)grow * HID_C + kt + kv * 4);
                float4 bv = *reinterpret_cast<const float4*>(b1 + kt + kv * 4);
                v.x = fmaxf(v.x + bv.x, 0.f);
                v.y = fmaxf(v.y + bv.y, 0.f);
                v.z = fmaxf(v.z + bv.z, 0.f);
                v.w = fmaxf(v.w + bv.w, 0.f);
            }
            As[kv * 4 + 0][r] = v.x;
            As[kv * 4 + 1][r] = v.y;
            As[kv * 4 + 2][r] = v.z;
            As[kv * 4 + 3][r] = v.w;
        }
#pragma unroll
        for (int i = 0; i < 4; i++) {
            int idx = tid + i * 128;
            int kk  = idx >> 4;
            int nv  = idx & 15;
            *reinterpret_cast<float4*>(&Bs[kk][nv * 4]) =
                *reinterpret_cast<const float4*>(W2 + (size_t)(kt + kk) * OUT_C + nv * 4);
        }
        __syncthreads();

#pragma unroll
        for (int k = 0; k < 32; k++) {
            float a[8], b[8];
            *reinterpret_cast<float4*>(&a[0]) = *reinterpret_cast<float4*>(&As[k][ty * 8]);
            *reinterpret_cast<float4*>(&a[4]) = *reinterpret_cast<float4*>(&As[k][ty * 8 + 4]);
            *reinterpret_cast<float4*>(&b[0]) = *reinterpret_cast<float4*>(&Bs[k][tx * 8]);
            *reinterpret_cast<float4*>(&b[4]) = *reinterpret_cast<float4*>(&Bs[k][tx * 8 + 4]);
#pragma unroll
            for (int i = 0; i < 8; i++)
#pragma unroll
                for (int j = 0; j < 8; j++) acc[i][j] += a[i] * b[j];
        }
        __syncthreads();
    }

#pragma unroll
    for (int i = 0; i < 8; i++) {
        int grow = rowBase + ty * 8 + i;
        if (grow < M) {
#pragma unroll
            for (int j = 0; j < 8; j += 4)
                *reinterpret_cast<float4*>(g_h2 + (size_t)grow * OUT_C + tx * 8 + j) =
                    make_float4(acc[i][j], acc[i][j + 1], acc[i][j + 2], acc[i][j + 3]);
        }
    }
}

// scatter2: out[dst] += h2[src], 64 ch. One warp per edge, float2 per lane.
__global__ __launch_bounds__(256) void scatter2_kernel(
    const int* __restrict__ ei, float* __restrict__ out, int E)
{
    int e    = (blockIdx.x * blockDim.x + threadIdx.x) >> 5;
    int lane = threadIdx.x & 31;
    if (e >= E) return;
    int s, d;
    load_sd(ei, e, E, g_idx_is64, s, d);
    float2 v = *reinterpret_cast<const float2*>(g_h2 + (size_t)s * OUT_C + lane * 2);
    float* a = out + (size_t)d * OUT_C + lane * 2;
    asm volatile("red.global.add.v2.f32 [%0], {%1,%2};"
                 :: "l"(a), "f"(v.x), "f"(v.y) : "memory");
}

extern "C" void kernel_launch(void* const* d_in, const int* in_sizes, int n_in,
                              void* d_out, int out_size)
{
    const float* x   = (const float*)d_in[0];
    const int*   ei  = (const int*)d_in[1];   // 32-bit word view; dtype detected on device
    const float* ew  = (const float*)d_in[2];
    const float* W1  = (const float*)d_in[3];
    const float* b1  = (const float*)d_in[4];
    const float* W2  = (const float*)d_in[5];
    const float* b2  = (const float*)d_in[6];
    float*       out = (float*)d_out;

    const int N = in_sizes[0] / IN_C;   // 50000
    const int E = in_sizes[2];          // 800000

    detect_idx_kernel<<<1, 1>>>(ei);
    zero_agg_kernel<<<2048, 256>>>(N * HID_C / 4);
    gemm1_kernel<<<(N + 63) / 64, 128>>>(x, W1, N);
    scatter1_kernel<<<(E * 32 + 255) / 256, 256>>>(ei, ew, E);
    init_out_kernel<<<2048, 256>>>(out, b2, out_size / 4);
    gemm2_kernel<<<(N + 127) / 128, 128>>>(W2, b1, N);
    scatter2_kernel<<<(E * 32 + 255) / 256, 256>>>(ei, out, E);
}

// round 3
// speedup vs baseline: 1.5107x; 1.5107x over previous
#include <cuda_runtime.h>
#include <cstdint>

#define NODES_MAX 50048
#define EDGES_MAX 800000
#define IN_C  128
#define HID_C 128
#define OUT_C 64

// ---------------- device scratch ----------------
__device__ float g_h   [(size_t)NODES_MAX * HID_C];   // x @ W1
__device__ float g_agg [(size_t)NODES_MAX * HID_C];   // aggregated layer 1
__device__ float g_h2  [(size_t)NODES_MAX * OUT_C];   // relu(agg+b1) @ W2
__device__ int   g_idx_is64;

// CSR-by-dst scratch
__device__ int   g_counts [NODES_MAX];
__device__ int   g_partial[NODES_MAX];
__device__ int   g_bsum   [64];
__device__ int   g_row_off[NODES_MAX + 1];
__device__ int   g_cursor [NODES_MAX];
__device__ int   g_csr_src[EDGES_MAX];
__device__ float g_csr_w  [EDGES_MAX];

// ---------------- index dtype detection (warp-parallel) ----------------
// int64 indices < 50000 -> every odd 32-bit word is 0.
__global__ void detect_idx_kernel(const int* __restrict__ ei_words) {
    int lane = threadIdx.x & 31;
    int bad = 0;
    for (int k = lane; k < 1024; k += 32)
        if (ei_words[2 * k + 1] != 0) bad = 1;
    bad = __any_sync(0xffffffffu, bad);
    if (lane == 0) g_idx_is64 = bad ? 0 : 1;
}

__device__ __forceinline__ void load_sd(const int* __restrict__ ei, int e, int E,
                                        int is64, int& s, int& d) {
    if (is64) { s = ei[2 * e]; d = ei[2 * E + 2 * e]; }
    else      { s = ei[e];     d = ei[E + e]; }
}

__device__ __forceinline__ int load_d(const int* __restrict__ ei, int e, int E, int is64) {
    return is64 ? ei[2 * E + 2 * e] : ei[E + e];
}

// ---------------- CSR build ----------------
__global__ void zero_counts_kernel(int n) {
    int i = blockIdx.x * blockDim.x + threadIdx.x;
    if (i < n) g_counts[i] = 0;
}

__global__ void hist_kernel(const int* __restrict__ ei, int E) {
    int e = blockIdx.x * blockDim.x + threadIdx.x;
    if (e >= E) return;
    int d = load_d(ei, e, E, g_idx_is64);
    atomicAdd(&g_counts[d], 1);
}

// Phase A: per-block exclusive scan of counts (1024 elems/block), block sums out.
__global__ __launch_bounds__(1024) void scan_local_kernel(int n) {
    __shared__ int sh[1024];
    int t = threadIdx.x;
    int idx = blockIdx.x * 1024 + t;
    int v = (idx < n) ? g_counts[idx] : 0;
    sh[t] = v;
    __syncthreads();
#pragma unroll
    for (int off = 1; off < 1024; off <<= 1) {
        int x = (t >= off) ? sh[t - off] : 0;
        __syncthreads();
        sh[t] += x;
        __syncthreads();
    }
    if (idx < n) g_partial[idx] = sh[t] - v;    // exclusive
    if (t == 1023) g_bsum[blockIdx.x] = sh[1023];
}

// Phase B: serial scan of <=64 block sums (tiny).
__global__ void scan_bsum_kernel(int nb) {
    if (threadIdx.x == 0) {
        int acc = 0;
        for (int i = 0; i < nb; i++) { int v = g_bsum[i]; g_bsum[i] = acc; acc += v; }
    }
}

// Phase C: finalize row offsets, zero cursors.
__global__ __launch_bounds__(1024) void scan_add_kernel(int n, int E) {
    int idx = blockIdx.x * 1024 + threadIdx.x;
    if (idx < n) {
        g_row_off[idx] = g_partial[idx] + g_bsum[idx >> 10];
        g_cursor[idx]  = 0;
    } else if (idx == n) {
        g_row_off[n] = E;
    }
}

__global__ void fill_kernel(const int* __restrict__ ei, const float* __restrict__ ew, int E) {
    int e = blockIdx.x * blockDim.x + threadIdx.x;
    if (e >= E) return;
    int s, d;
    load_sd(ei, e, E, g_idx_is64, s, d);
    int pos = g_row_off[d] + atomicAdd(&g_cursor[d], 1);
    g_csr_src[pos] = s;
    g_csr_w[pos]   = ew[e];
}

// ---------------- GEMM1: h[M,128] = x[M,128] @ W1[128,128] ----------------
__global__ __launch_bounds__(128) void gemm1_kernel(
    const float* __restrict__ x, const float* __restrict__ W, int M)
{
    __shared__ float As[32][64];
    __shared__ float Bs[32][128];

    const int tid = threadIdx.x;
    const int ty  = tid >> 4;
    const int tx  = tid & 15;
    const int rowBase = blockIdx.x * 64;

    float acc[8][8];
#pragma unroll
    for (int i = 0; i < 8; i++)
#pragma unroll
        for (int j = 0; j < 8; j++) acc[i][j] = 0.f;

    for (int kt = 0; kt < IN_C; kt += 32) {
#pragma unroll
        for (int i = 0; i < 4; i++) {
            int idx = tid + i * 128;
            int r   = idx >> 3;
            int kv  = idx & 7;
            int grow = rowBase + r;
            float4 v = make_float4(0.f, 0.f, 0.f, 0.f);
            if (grow < M)
                v = *reinterpret_cast<const float4*>(x + (size_t)grow * IN_C + kt + kv * 4);
            As[kv * 4 + 0][r] = v.x;
            As[kv * 4 + 1][r] = v.y;
            As[kv * 4 + 2][r] = v.z;
            As[kv * 4 + 3][r] = v.w;
        }
#pragma unroll
        for (int i = 0; i < 8; i++) {
            int idx = tid + i * 128;
            int kk  = idx >> 5;
            int nv  = idx & 31;
            *reinterpret_cast<float4*>(&Bs[kk][nv * 4]) =
                *reinterpret_cast<const float4*>(W + (size_t)(kt + kk) * HID_C + nv * 4);
        }
        __syncthreads();

#pragma unroll
        for (int k = 0; k < 32; k++) {
            float a[8], b[8];
            *reinterpret_cast<float4*>(&a[0]) = *reinterpret_cast<float4*>(&As[k][ty * 8]);
            *reinterpret_cast<float4*>(&a[4]) = *reinterpret_cast<float4*>(&As[k][ty * 8 + 4]);
            *reinterpret_cast<float4*>(&b[0]) = *reinterpret_cast<float4*>(&Bs[k][tx * 8]);
            *reinterpret_cast<float4*>(&b[4]) = *reinterpret_cast<float4*>(&Bs[k][tx * 8 + 4]);
#pragma unroll
            for (int i = 0; i < 8; i++)
#pragma unroll
                for (int j = 0; j < 8; j++) acc[i][j] += a[i] * b[j];
        }
        __syncthreads();
    }

#pragma unroll
    for (int i = 0; i < 8; i++) {
        int grow = rowBase + ty * 8 + i;
        if (grow < M) {
#pragma unroll
            for (int j = 0; j < 8; j += 4)
                *reinterpret_cast<float4*>(g_h + (size_t)grow * HID_C + tx * 8 + j) =
                    make_float4(acc[i][j], acc[i][j + 1], acc[i][j + 2], acc[i][j + 3]);
        }
    }
}

// ---------------- gather1: agg[i] = sum_j w_j * h[src_j], 128 ch ----------------
// One warp per node; lane owns a float4 (32*4 = 128 ch). 2-way edge unroll for MLP.
__global__ __launch_bounds__(256) void gather1_kernel(int n)
{
    int node = (blockIdx.x * blockDim.x + threadIdx.x) >> 5;
    int lane = threadIdx.x & 31;
    if (node >= n) return;
    int beg = g_row_off[node];
    int end = g_row_off[node + 1];

    float4 acc0 = make_float4(0.f, 0.f, 0.f, 0.f);
    float4 acc1 = make_float4(0.f, 0.f, 0.f, 0.f);
    int j = beg;
    for (; j + 1 < end; j += 2) {
        int   s0 = g_csr_src[j],   s1 = g_csr_src[j + 1];
        float w0 = g_csr_w[j],     w1 = g_csr_w[j + 1];
        float4 v0 = *reinterpret_cast<const float4*>(g_h + (size_t)s0 * HID_C + lane * 4);
        float4 v1 = *reinterpret_cast<const float4*>(g_h + (size_t)s1 * HID_C + lane * 4);
        acc0.x += w0 * v0.x; acc0.y += w0 * v0.y; acc0.z += w0 * v0.z; acc0.w += w0 * v0.w;
        acc1.x += w1 * v1.x; acc1.y += w1 * v1.y; acc1.z += w1 * v1.z; acc1.w += w1 * v1.w;
    }
    if (j < end) {
        int   s0 = g_csr_src[j];
        float w0 = g_csr_w[j];
        float4 v0 = *reinterpret_cast<const float4*>(g_h + (size_t)s0 * HID_C + lane * 4);
        acc0.x += w0 * v0.x; acc0.y += w0 * v0.y; acc0.z += w0 * v0.z; acc0.w += w0 * v0.w;
    }
    acc0.x += acc1.x; acc0.y += acc1.y; acc0.z += acc1.z; acc0.w += acc1.w;
    *reinterpret_cast<float4*>(g_agg + (size_t)node * HID_C + lane * 4) = acc0;
}

// ---------------- GEMM2: h2[M,64] = relu(agg[M,128]+b1) @ W2[128,64] ----------------
__global__ __launch_bounds__(128) void gemm2_kernel(
    const float* __restrict__ W2, const float* __restrict__ b1, int M)
{
    __shared__ float As[32][128];
    __shared__ float Bs[32][64];

    const int tid = threadIdx.x;
    const int ty  = tid >> 3;
    const int tx  = tid & 7;
    const int rowBase = blockIdx.x * 128;

    float acc[8][8];
#pragma unroll
    for (int i = 0; i < 8; i++)
#pragma unroll
        for (int j = 0; j < 8; j++) acc[i][j] = 0.f;

    for (int kt = 0; kt < HID_C; kt += 32) {
#pragma unroll
        for (int i = 0; i < 8; i++) {
            int idx = tid + i * 128;
            int r   = idx >> 3;
            int kv  = idx & 7;
            int grow = rowBase + r;
            float4 v = make_float4(0.f, 0.f, 0.f, 0.f);
            if (grow < M) {
                v = *reinterpret_cast<const float4*>(g_agg + (size_t)grow * HID_C + kt + kv * 4);
                float4 bv = *reinterpret_cast<const float4*>(b1 + kt + kv * 4);
                v.x = fmaxf(v.x + bv.x, 0.f);
                v.y = fmaxf(v.y + bv.y, 0.f);
                v.z = fmaxf(v.z + bv.z, 0.f);
                v.w = fmaxf(v.w + bv.w, 0.f);
            }
            As[kv * 4 + 0][r] = v.x;
            As[kv * 4 + 1][r] = v.y;
            As[kv * 4 + 2][r] = v.z;
            As[kv * 4 + 3][r] = v.w;
        }
#pragma unroll
        for (int i = 0; i < 4; i++) {
            int idx = tid + i * 128;
            int kk  = idx >> 4;
            int nv  = idx & 15;
            *reinterpret_cast<float4*>(&Bs[kk][nv * 4]) =
                *reinterpret_cast<const float4*>(W2 + (size_t)(kt + kk) * OUT_C + nv * 4);
        }
        __syncthreads();

#pragma unroll
        for (int k = 0; k < 32; k++) {
            float a[8], b[8];
            *reinterpret_cast<float4*>(&a[0]) = *reinterpret_cast<float4*>(&As[k][ty * 8]);
            *reinterpret_cast<float4*>(&a[4]) = *reinterpret_cast<float4*>(&As[k][ty * 8 + 4]);
            *reinterpret_cast<float4*>(&b[0]) = *reinterpret_cast<float4*>(&Bs[k][tx * 8]);
            *reinterpret_cast<float4*>(&b[4]) = *reinterpret_cast<float4*>(&Bs[k][tx * 8 + 4]);
#pragma unroll
            for (int i = 0; i < 8; i++)
#pragma unroll
                for (int j = 0; j < 8; j++) acc[i][j] += a[i] * b[j];
        }
        __syncthreads();
    }

#pragma unroll
    for (int i = 0; i < 8; i++) {
        int grow = rowBase + ty * 8 + i;
        if (grow < M) {
#pragma unroll
            for (int j = 0; j < 8; j += 4)
                *reinterpret_cast<float4*>(g_h2 + (size_t)grow * OUT_C + tx * 8 + j) =
                    make_float4(acc[i][j], acc[i][j + 1], acc[i][j + 2], acc[i][j + 3]);
        }
    }
}

// ---------------- gather2: out[i] = b2 + sum_j h2[src_j], 64 ch ----------------
// One warp per node; lane owns a float2. Direct write, no init pass needed.
__global__ __launch_bounds__(256) void gather2_kernel(
    float* __restrict__ out, const float* __restrict__ b2, int n)
{
    int node = (blockIdx.x * blockDim.x + threadIdx.x) >> 5;
    int lane = threadIdx.x & 31;
    if (node >= n) return;
    int beg = g_row_off[node];
    int end = g_row_off[node + 1];

    float2 acc0 = make_float2(0.f, 0.f);
    float2 acc1 = make_float2(0.f, 0.f);
    int j = beg;
    for (; j + 1 < end; j += 2) {
        int s0 = g_csr_src[j], s1 = g_csr_src[j + 1];
        float2 v0 = *reinterpret_cast<const float2*>(g_h2 + (size_t)s0 * OUT_C + lane * 2);
        float2 v1 = *reinterpret_cast<const float2*>(g_h2 + (size_t)s1 * OUT_C + lane * 2);
        acc0.x += v0.x; acc0.y += v0.y;
        acc1.x += v1.x; acc1.y += v1.y;
    }
    if (j < end) {
        int s0 = g_csr_src[j];
        float2 v0 = *reinterpret_cast<const float2*>(g_h2 + (size_t)s0 * OUT_C + lane * 2);
        acc0.x += v0.x; acc0.y += v0.y;
    }
    float2 bv = *reinterpret_cast<const float2*>(b2 + lane * 2);
    acc0.x += acc1.x + bv.x;
    acc0.y += acc1.y + bv.y;
    *reinterpret_cast<float2*>(out + (size_t)node * OUT_C + lane * 2) = acc0;
}

// ---------------- launch ----------------
extern "C" void kernel_launch(void* const* d_in, const int* in_sizes, int n_in,
                              void* d_out, int out_size)
{
    const float* x   = (const float*)d_in[0];
    const int*   ei  = (const int*)d_in[1];   // dtype detected on device
    const float* ew  = (const float*)d_in[2];
    const float* W1  = (const float*)d_in[3];
    const float* b1  = (const float*)d_in[4];
    const float* W2  = (const float*)d_in[5];
    const float* b2  = (const float*)d_in[6];
    float*       out = (float*)d_out;

    const int N = in_sizes[0] / IN_C;   // 50000
    const int E = in_sizes[2];          // 800000
    const int nScanBlocks = (N + 1023) / 1024;

    // index dtype + CSR build (interleaved with gemm1, which is independent)
    detect_idx_kernel<<<1, 32>>>(ei);
    zero_counts_kernel<<<(N + 255) / 256, 256>>>(N);
    gemm1_kernel<<<(N + 63) / 64, 128>>>(x, W1, N);
    hist_kernel<<<(E + 255) / 256, 256>>>(ei, E);
    scan_local_kernel<<<nScanBlocks, 1024>>>(N);
    scan_bsum_kernel<<<1, 1>>>(nScanBlocks);
    scan_add_kernel<<<nScanBlocks + 1, 1024>>>(N, E);
    fill_kernel<<<(E + 255) / 256, 256>>>(ei, ew, E);

    // layer 1 aggregate
    gather1_kernel<<<(N * 32 + 255) / 256, 256>>>(N);

    // layer 2
    gemm2_kernel<<<(N + 127) / 128, 128>>>(W2, b1, N);
    gather2_kernel<<<(N * 32 + 255) / 256, 256>>>(out, b2, N);
}

// round 4
// speedup vs baseline: 1.7081x; 1.1307x over previous
#include <cuda_runtime.h>
#include <cstdint>

#define NODES_MAX 50048
#define EDGES_MAX 800000
#define IN_C  128
#define HID_C 128
#define OUT_C 64

// ---------------- device scratch ----------------
__device__ float  g_h   [(size_t)NODES_MAX * HID_C];   // x @ W1
__device__ float  g_agg [(size_t)NODES_MAX * HID_C];   // aggregated layer 1
__device__ float  g_h2  [(size_t)NODES_MAX * OUT_C];   // relu(agg+b1) @ W2
__device__ int    g_idx_is64;

// CSR-by-dst scratch
__device__ int    g_counts [NODES_MAX];
__device__ int    g_partial[NODES_MAX];
__device__ int    g_bsum   [64];
__device__ int    g_row_off[NODES_MAX + 1];
__device__ int    g_cursor [NODES_MAX];
__device__ float2 g_csr_sw [EDGES_MAX];   // .x = src index (as int bits), .y = weight

// ---------------- index dtype detection (warp-parallel) ----------------
// int64 indices < 50000 -> every odd 32-bit word is 0.
__global__ void detect_idx_kernel(const int* __restrict__ ei_words) {
    int lane = threadIdx.x & 31;
    int bad = 0;
    for (int k = lane; k < 1024; k += 32)
        if (ei_words[2 * k + 1] != 0) bad = 1;
    bad = __any_sync(0xffffffffu, bad);
    if (lane == 0) g_idx_is64 = bad ? 0 : 1;
}

__device__ __forceinline__ void load_sd(const int* __restrict__ ei, int e, int E,
                                        int is64, int& s, int& d) {
    if (is64) { s = ei[2 * e]; d = ei[2 * E + 2 * e]; }
    else      { s = ei[e];     d = ei[E + e]; }
}

__device__ __forceinline__ int load_d(const int* __restrict__ ei, int e, int E, int is64) {
    return is64 ? ei[2 * E + 2 * e] : ei[E + e];
}

// ---------------- CSR build ----------------
__global__ void zero_counts_kernel(int n) {
    int i = blockIdx.x * blockDim.x + threadIdx.x;
    if (i < n) g_counts[i] = 0;
}

// 4 edges per thread for MLP (hist was latency-bound at issue=8.8%).
__global__ void hist_kernel(const int* __restrict__ ei, int E) {
    int base = (blockIdx.x * blockDim.x + threadIdx.x) * 4;
    int is64 = g_idx_is64;
    int d0 = -1, d1 = -1, d2 = -1, d3 = -1;
    if (base + 0 < E) d0 = load_d(ei, base + 0, E, is64);
    if (base + 1 < E) d1 = load_d(ei, base + 1, E, is64);
    if (base + 2 < E) d2 = load_d(ei, base + 2, E, is64);
    if (base + 3 < E) d3 = load_d(ei, base + 3, E, is64);
    if (d0 >= 0) atomicAdd(&g_counts[d0], 1);
    if (d1 >= 0) atomicAdd(&g_counts[d1], 1);
    if (d2 >= 0) atomicAdd(&g_counts[d2], 1);
    if (d3 >= 0) atomicAdd(&g_counts[d3], 1);
}

// Phase A: per-block exclusive scan of counts (1024 elems/block), block sums out.
__global__ __launch_bounds__(1024) void scan_local_kernel(int n) {
    __shared__ int sh[1024];
    int t = threadIdx.x;
    int idx = blockIdx.x * 1024 + t;
    int v = (idx < n) ? g_counts[idx] : 0;
    sh[t] = v;
    __syncthreads();
#pragma unroll
    for (int off = 1; off < 1024; off <<= 1) {
        int x = (t >= off) ? sh[t - off] : 0;
        __syncthreads();
        sh[t] += x;
        __syncthreads();
    }
    if (idx < n) g_partial[idx] = sh[t] - v;    // exclusive
    if (t == 1023) g_bsum[blockIdx.x] = sh[1023];
}

// Phase B: serial scan of <=64 block sums (tiny).
__global__ void scan_bsum_kernel(int nb) {
    if (threadIdx.x == 0) {
        int acc = 0;
        for (int i = 0; i < nb; i++) { int v = g_bsum[i]; g_bsum[i] = acc; acc += v; }
    }
}

// Phase C: finalize row offsets, zero cursors.
__global__ __launch_bounds__(1024) void scan_add_kernel(int n, int E) {
    int idx = blockIdx.x * 1024 + threadIdx.x;
    if (idx < n) {
        g_row_off[idx] = g_partial[idx] + g_bsum[idx >> 10];
        g_cursor[idx]  = 0;
    } else if (idx == n) {
        g_row_off[n] = E;
    }
}

__global__ void fill_kernel(const int* __restrict__ ei, const float* __restrict__ ew, int E) {
    int e = blockIdx.x * blockDim.x + threadIdx.x;
    if (e >= E) return;
    int s, d;
    load_sd(ei, e, E, g_idx_is64, s, d);
    int pos = g_row_off[d] + atomicAdd(&g_cursor[d], 1);
    g_csr_sw[pos] = make_float2(__int_as_float(s), ew[e]);
}

// ---------------- GEMM1: h[M,128] = x[M,128] @ W1[128,128] ----------------
__global__ __launch_bounds__(128) void gemm1_kernel(
    const float* __restrict__ x, const float* __restrict__ W, int M)
{
    __shared__ float As[32][64];
    __shared__ float Bs[32][128];

    const int tid = threadIdx.x;
    const int ty  = tid >> 4;
    const int tx  = tid & 15;
    const int rowBase = blockIdx.x * 64;

    float acc[8][8];
#pragma unroll
    for (int i = 0; i < 8; i++)
#pragma unroll
        for (int j = 0; j < 8; j++) acc[i][j] = 0.f;

    for (int kt = 0; kt < IN_C; kt += 32) {
#pragma unroll
        for (int i = 0; i < 4; i++) {
            int idx = tid + i * 128;
            int r   = idx >> 3;
            int kv  = idx & 7;
            int grow = rowBase + r;
            float4 v = make_float4(0.f, 0.f, 0.f, 0.f);
            if (grow < M)
                v = *reinterpret_cast<const float4*>(x + (size_t)grow * IN_C + kt + kv * 4);
            As[kv * 4 + 0][r] = v.x;
            As[kv * 4 + 1][r] = v.y;
            As[kv * 4 + 2][r] = v.z;
            As[kv * 4 + 3][r] = v.w;
        }
#pragma unroll
        for (int i = 0; i < 8; i++) {
            int idx = tid + i * 128;
            int kk  = idx >> 5;
            int nv  = idx & 31;
            *reinterpret_cast<float4*>(&Bs[kk][nv * 4]) =
                *reinterpret_cast<const float4*>(W + (size_t)(kt + kk) * HID_C + nv * 4);
        }
        __syncthreads();

#pragma unroll
        for (int k = 0; k < 32; k++) {
            float a[8], b[8];
            *reinterpret_cast<float4*>(&a[0]) = *reinterpret_cast<float4*>(&As[k][ty * 8]);
            *reinterpret_cast<float4*>(&a[4]) = *reinterpret_cast<float4*>(&As[k][ty * 8 + 4]);
            *reinterpret_cast<float4*>(&b[0]) = *reinterpret_cast<float4*>(&Bs[k][tx * 8]);
            *reinterpret_cast<float4*>(&b[4]) = *reinterpret_cast<float4*>(&Bs[k][tx * 8 + 4]);
#pragma unroll
            for (int i = 0; i < 8; i++)
#pragma unroll
                for (int j = 0; j < 8; j++) acc[i][j] += a[i] * b[j];
        }
        __syncthreads();
    }

#pragma unroll
    for (int i = 0; i < 8; i++) {
        int grow = rowBase + ty * 8 + i;
        if (grow < M) {
#pragma unroll
            for (int j = 0; j < 8; j += 4)
                *reinterpret_cast<float4*>(g_h + (size_t)grow * HID_C + tx * 8 + j) =
                    make_float4(acc[i][j], acc[i][j + 1], acc[i][j + 2], acc[i][j + 3]);
        }
    }
}

// ---------------- gather1: agg[i] = sum_j w_j * h[src_j], 128 ch ----------------
// One warp per node; lane owns a float4. 2-way edge unroll for MLP.
__global__ __launch_bounds__(256) void gather1_kernel(int n)
{
    int node = (blockIdx.x * blockDim.x + threadIdx.x) >> 5;
    int lane = threadIdx.x & 31;
    if (node >= n) return;
    int beg = g_row_off[node];
    int end = g_row_off[node + 1];

    float4 acc0 = make_float4(0.f, 0.f, 0.f, 0.f);
    float4 acc1 = make_float4(0.f, 0.f, 0.f, 0.f);
    int j = beg;
    for (; j + 1 < end; j += 2) {
        float2 p0 = g_csr_sw[j];
        float2 p1 = g_csr_sw[j + 1];
        int   s0 = __float_as_int(p0.x);
        int   s1 = __float_as_int(p1.x);
        float w0 = p0.y, w1 = p1.y;
        float4 v0 = *reinterpret_cast<const float4*>(g_h + (size_t)s0 * HID_C + lane * 4);
        float4 v1 = *reinterpret_cast<const float4*>(g_h + (size_t)s1 * HID_C + lane * 4);
        acc0.x += w0 * v0.x; acc0.y += w0 * v0.y; acc0.z += w0 * v0.z; acc0.w += w0 * v0.w;
        acc1.x += w1 * v1.x; acc1.y += w1 * v1.y; acc1.z += w1 * v1.z; acc1.w += w1 * v1.w;
    }
    if (j < end) {
        float2 p0 = g_csr_sw[j];
        int   s0 = __float_as_int(p0.x);
        float w0 = p0.y;
        float4 v0 = *reinterpret_cast<const float4*>(g_h + (size_t)s0 * HID_C + lane * 4);
        acc0.x += w0 * v0.x; acc0.y += w0 * v0.y; acc0.z += w0 * v0.z; acc0.w += w0 * v0.w;
    }
    acc0.x += acc1.x; acc0.y += acc1.y; acc0.z += acc1.z; acc0.w += acc1.w;
    *reinterpret_cast<float4*>(g_agg + (size_t)node * HID_C + lane * 4) = acc0;
}

// ---------------- GEMM2: h2[M,64] = relu(agg[M,128]+b1) @ W2[128,64] ----------------
__global__ __launch_bounds__(128) void gemm2_kernel(
    const float* __restrict__ W2, const float* __restrict__ b1, int M)
{
    __shared__ float As[32][128];
    __shared__ float Bs[32][64];

    const int tid = threadIdx.x;
    const int ty  = tid >> 3;
    const int tx  = tid & 7;
    const int rowBase = blockIdx.x * 128;

    float acc[8][8];
#pragma unroll
    for (int i = 0; i < 8; i++)
#pragma unroll
        for (int j = 0; j < 8; j++) acc[i][j] = 0.f;

    for (int kt = 0; kt < HID_C; kt += 32) {
#pragma unroll
        for (int i = 0; i < 8; i++) {
            int idx = tid + i * 128;
            int r   = idx >> 3;
            int kv  = idx & 7;
            int grow = rowBase + r;
            float4 v = make_float4(0.f, 0.f, 0.f, 0.f);
            if (grow < M) {
                v = *reinterpret_cast<const float4*>(g_agg + (size_t)grow * HID_C + kt + kv * 4);
                float4 bv = *reinterpret_cast<const float4*>(b1 + kt + kv * 4);
                v.x = fmaxf(v.x + bv.x, 0.f);
                v.y = fmaxf(v.y + bv.y, 0.f);
                v.z = fmaxf(v.z + bv.z, 0.f);
                v.w = fmaxf(v.w + bv.w, 0.f);
            }
            As[kv * 4 + 0][r] = v.x;
            As[kv * 4 + 1][r] = v.y;
            As[kv * 4 + 2][r] = v.z;
            As[kv * 4 + 3][r] = v.w;
        }
#pragma unroll
        for (int i = 0; i < 4; i++) {
            int idx = tid + i * 128;
            int kk  = idx >> 4;
            int nv  = idx & 15;
            *reinterpret_cast<float4*>(&Bs[kk][nv * 4]) =
                *reinterpret_cast<const float4*>(W2 + (size_t)(kt + kk) * OUT_C + nv * 4);
        }
        __syncthreads();

#pragma unroll
        for (int k = 0; k < 32; k++) {
            float a[8], b[8];
            *reinterpret_cast<float4*>(&a[0]) = *reinterpret_cast<float4*>(&As[k][ty * 8]);
            *reinterpret_cast<float4*>(&a[4]) = *reinterpret_cast<float4*>(&As[k][ty * 8 + 4]);
            *reinterpret_cast<float4*>(&b[0]) = *reinterpret_cast<float4*>(&Bs[k][tx * 8]);
            *reinterpret_cast<float4*>(&b[4]) = *reinterpret_cast<float4*>(&Bs[k][tx * 8 + 4]);
#pragma unroll
            for (int i = 0; i < 8; i++)
#pragma unroll
                for (int j = 0; j < 8; j++) acc[i][j] += a[i] * b[j];
        }
        __syncthreads();
    }

#pragma unroll
    for (int i = 0; i < 8; i++) {
        int grow = rowBase + ty * 8 + i;
        if (grow < M) {
#pragma unroll
            for (int j = 0; j < 8; j += 4)
                *reinterpret_cast<float4*>(g_h2 + (size_t)grow * OUT_C + tx * 8 + j) =
                    make_float4(acc[i][j], acc[i][j + 1], acc[i][j + 2], acc[i][j + 3]);
        }
    }
}

// ---------------- gather2: out[i] = b2 + sum_j h2[src_j], 64 ch ----------------
__global__ __launch_bounds__(256) void gather2_kernel(
    float* __restrict__ out, const float* __restrict__ b2, int n)
{
    int node = (blockIdx.x * blockDim.x + threadIdx.x) >> 5;
    int lane = threadIdx.x & 31;
    if (node >= n) return;
    int beg = g_row_off[node];
    int end = g_row_off[node + 1];

    float2 acc0 = make_float2(0.f, 0.f);
    float2 acc1 = make_float2(0.f, 0.f);
    int j = beg;
    for (; j + 1 < end; j += 2) {
        int s0 = __float_as_int(g_csr_sw[j].x);
        int s1 = __float_as_int(g_csr_sw[j + 1].x);
        float2 v0 = *reinterpret_cast<const float2*>(g_h2 + (size_t)s0 * OUT_C + lane * 2);
        float2 v1 = *reinterpret_cast<const float2*>(g_h2 + (size_t)s1 * OUT_C + lane * 2);
        acc0.x += v0.x; acc0.y += v0.y;
        acc1.x += v1.x; acc1.y += v1.y;
    }
    if (j < end) {
        int s0 = __float_as_int(g_csr_sw[j].x);
        float2 v0 = *reinterpret_cast<const float2*>(g_h2 + (size_t)s0 * OUT_C + lane * 2);
        acc0.x += v0.x; acc0.y += v0.y;
    }
    float2 bv = *reinterpret_cast<const float2*>(b2 + lane * 2);
    acc0.x += acc1.x + bv.x;
    acc0.y += acc1.y + bv.y;
    *reinterpret_cast<float2*>(out + (size_t)node * OUT_C + lane * 2) = acc0;
}

// ---------------- launch ----------------
extern "C" void kernel_launch(void* const* d_in, const int* in_sizes, int n_in,
                              void* d_out, int out_size)
{
    const float* x   = (const float*)d_in[0];
    const int*   ei  = (const int*)d_in[1];   // dtype detected on device
    const float* ew  = (const float*)d_in[2];
    const float* W1  = (const float*)d_in[3];
    const float* b1  = (const float*)d_in[4];
    const float* W2  = (const float*)d_in[5];
    const float* b2  = (const float*)d_in[6];
    float*       out = (float*)d_out;

    const int N = in_sizes[0] / IN_C;   // 50000
    const int E = in_sizes[2];          // 800000
    const int nScanBlocks = (N + 1023) / 1024;

    // Lazy-once side stream + fork/join events (created outside any capture;
    // no device-memory allocation involved).
    static cudaStream_t s_side = nullptr;
    static cudaEvent_t  s_fork = nullptr, s_join = nullptr;
    if (s_side == nullptr) {
        cudaStreamCreateWithFlags(&s_side, cudaStreamNonBlocking);
        cudaEventCreateWithFlags(&s_fork, cudaEventDisableTiming);
        cudaEventCreateWithFlags(&s_join, cudaEventDisableTiming);
    }

    // main: detect dtype (needed by both branches)
    detect_idx_kernel<<<1, 32>>>(ei);

    // fork: CSR build on side stream, concurrent with gemm1 on main
    cudaEventRecord(s_fork, 0);
    cudaStreamWaitEvent(s_side, s_fork, 0);

    zero_counts_kernel<<<(N + 255) / 256, 256, 0, s_side>>>(N);
    hist_kernel<<<(E / 4 + 255) / 256, 256, 0, s_side>>>(ei, E);
    scan_local_kernel<<<nScanBlocks, 1024, 0, s_side>>>(N);
    scan_bsum_kernel<<<1, 1, 0, s_side>>>(nScanBlocks);
    scan_add_kernel<<<nScanBlocks + 1, 1024, 0, s_side>>>(N, E);
    fill_kernel<<<(E + 255) / 256, 256, 0, s_side>>>(ei, ew, E);
    cudaEventRecord(s_join, s_side);

    // main: dense layer-1 GEMM (independent of CSR)
    gemm1_kernel<<<(N + 63) / 64, 128>>>(x, W1, N);

    // join: gather1 needs both gemm1 (main) and CSR (side)
    cudaStreamWaitEvent(0, s_join, 0);

    gather1_kernel<<<(N * 32 + 255) / 256, 256>>>(N);
    gemm2_kernel<<<(N + 127) / 128, 128>>>(W2, b1, N);
    gather2_kernel<<<(N * 32 + 255) / 256, 256>>>(out, b2, N);
}